// round 5
// baseline (speedup 1.0000x reference)
#include <cuda_runtime.h>
#include <math.h>

// Problem dims (fixed by the reference)
#define B_   16
#define TQ   512
#define TK   1024
#define DD   512

// SGEMM tiling
#define BM 128
#define BN 64
#define BK 16
#define TM 8
#define TN 8
#define NTHREADS 128   // (BM/TM)*(BN/TN)

// 16 MB scratch for Q' = linear_q(query)  (device global: allowed, no alloc)
__device__ float g_qprime[(size_t)B_ * TQ * DD];

// ---- packed fp32x2 helpers (Blackwell FFMA2: 2x fp32 throughput) ----
__device__ __forceinline__ void fma2(unsigned long long &d,
                                     unsigned long long a,
                                     unsigned long long b) {
    asm("fma.rn.f32x2 %0, %1, %2, %0;" : "+l"(d) : "l"(a), "l"(b));
}
__device__ __forceinline__ unsigned long long bcast2(float x) {
    unsigned long long r;
    asm("mov.b64 %0, {%1, %1};" : "=l"(r) : "f"(x));
    return r;
}
__device__ __forceinline__ float2 unpack2(unsigned long long v) {
    float2 r;
    asm("mov.b64 {%0, %1}, %2;" : "=f"(r.x), "=f"(r.y) : "l"(v));
    return r;
}

union F4U { float4 f; unsigned long long u[2]; };

// C[m,n] = alpha * sum_k A[m,k] * B(k,n) + bias[n]
//   BT_KMAJOR = true : B is [N,K] row-major (k contiguous)  -> NT GEMM
//   BT_KMAJOR = false: B is [K,N] row-major (n contiguous)  -> NN GEMM
// All dims are multiples of the tile sizes in this problem; no bounds checks.
template<bool BT_KMAJOR>
__global__ void __launch_bounds__(NTHREADS)
gemm_kernel(const float* __restrict__ A, int lda, long long sA,
            const float* __restrict__ Bm, int ldb, long long sB,
            float* __restrict__ C, int ldc, long long sC,
            int K,
            const float* __restrict__ bias,
            const float* __restrict__ scale)
{
    __shared__ float As[BK][BM + 4];
    __shared__ float Bs[BK][BN + 4];

    A  += (long long)blockIdx.z * sA;
    Bm += (long long)blockIdx.z * sB;
    C  += (long long)blockIdx.z * sC;

    const int m0 = blockIdx.y * BM;
    const int n0 = blockIdx.x * BN;
    const int tid = threadIdx.x;

    const int lrow = tid >> 2;          // 0..31  (k-major loader: row)
    const int lkv  = (tid & 3) * 4;     // 0,4,8,12 (k-vector within BK)
    const int tr = tid >> 3;            // 0..15  microtile row
    const int tc = tid & 7;             // 0..7   microtile col

    unsigned long long acc[TM][TN / 2];
    #pragma unroll
    for (int i = 0; i < TM; i++)
        #pragma unroll
        for (int j = 0; j < TN / 2; j++) acc[i][j] = 0ULL;

    for (int k0 = 0; k0 < K; k0 += BK) {
        // --- load A tile [BM x BK], store transposed As[k][m] ---
        #pragma unroll
        for (int i = 0; i < 4; i++) {
            int r = lrow + i * 32;
            float4 v = *(const float4*)(A + (long long)(m0 + r) * lda + (k0 + lkv));
            As[lkv + 0][r] = v.x; As[lkv + 1][r] = v.y;
            As[lkv + 2][r] = v.z; As[lkv + 3][r] = v.w;
        }
        // --- load B tile ---
        if (BT_KMAJOR) {
            // B[n,k] k-contiguous: [BN x BK], transpose into Bs[k][n]
            #pragma unroll
            for (int i = 0; i < 2; i++) {
                int r = lrow + i * 32;
                float4 v = *(const float4*)(Bm + (long long)(n0 + r) * ldb + (k0 + lkv));
                Bs[lkv + 0][r] = v.x; Bs[lkv + 1][r] = v.y;
                Bs[lkv + 2][r] = v.z; Bs[lkv + 3][r] = v.w;
            }
        } else {
            // B[k,n] n-contiguous: [BK x BN], direct copy
            #pragma unroll
            for (int i = 0; i < 2; i++) {
                int kk = (tid >> 4) + i * 8;
                int nv = (tid & 15) * 4;
                *(float4*)&Bs[kk][nv] =
                    *(const float4*)(Bm + (long long)(k0 + kk) * ldb + (n0 + nv));
            }
        }
        __syncthreads();

        #pragma unroll
        for (int k = 0; k < BK; k++) {
            F4U a0, a1, b0, b1;
            a0.f = *(const float4*)&As[k][tr * TM];
            a1.f = *(const float4*)&As[k][tr * TM + 4];
            b0.f = *(const float4*)&Bs[k][tc * TN];
            b1.f = *(const float4*)&Bs[k][tc * TN + 4];
            float av[8] = {a0.f.x, a0.f.y, a0.f.z, a0.f.w,
                           a1.f.x, a1.f.y, a1.f.z, a1.f.w};
            #pragma unroll
            for (int i = 0; i < TM; i++) {
                unsigned long long ai = bcast2(av[i]);
                fma2(acc[i][0], ai, b0.u[0]);
                fma2(acc[i][1], ai, b0.u[1]);
                fma2(acc[i][2], ai, b1.u[0]);
                fma2(acc[i][3], ai, b1.u[1]);
            }
        }
        __syncthreads();
    }

    const float alpha = scale ? __ldg(scale) : 1.0f;
    #pragma unroll
    for (int i = 0; i < TM; i++) {
        int m = m0 + tr * TM + i;
        float* crow = C + (long long)m * ldc + n0 + tc * TN;
        #pragma unroll
        for (int j = 0; j < TN / 2; j++) {
            float2 v = unpack2(acc[i][j]);
            float bv0 = bias ? bias[n0 + tc * TN + 2 * j]     : 0.0f;
            float bv1 = bias ? bias[n0 + tc * TN + 2 * j + 1] : 0.0f;
            v.x = v.x * alpha + bv0;
            v.y = v.y * alpha + bv1;
            *(float2*)(crow + 2 * j) = v;
        }
    }
}

// One warp per row: masked softmax over TK=1024 (fits in 32 float4 regs/warp).
__global__ void __launch_bounds__(128)
softmax_kernel(float* __restrict__ attn, const int* __restrict__ lens)
{
    int warp = (int)((blockIdx.x * blockDim.x + threadIdx.x) >> 5);
    int lane = threadIdx.x & 31;
    if (warp >= B_ * TQ) return;
    const int len = lens[warp / TQ];
    float4* row = (float4*)(attn + (size_t)warp * TK);

    float4 v[8];
    float mx = -INFINITY;
    #pragma unroll
    for (int i = 0; i < 8; i++) {
        v[i] = row[i * 32 + lane];
        int k = 4 * (i * 32 + lane);
        if (k + 0 < len) mx = fmaxf(mx, v[i].x);
        if (k + 1 < len) mx = fmaxf(mx, v[i].y);
        if (k + 2 < len) mx = fmaxf(mx, v[i].z);
        if (k + 3 < len) mx = fmaxf(mx, v[i].w);
    }
    #pragma unroll
    for (int o = 16; o > 0; o >>= 1)
        mx = fmaxf(mx, __shfl_xor_sync(0xFFFFFFFFu, mx, o));

    float sum = 0.0f;
    #pragma unroll
    for (int i = 0; i < 8; i++) {
        int k = 4 * (i * 32 + lane);
        v[i].x = (k + 0 < len) ? expf(v[i].x - mx) : 0.0f;
        v[i].y = (k + 1 < len) ? expf(v[i].y - mx) : 0.0f;
        v[i].z = (k + 2 < len) ? expf(v[i].z - mx) : 0.0f;
        v[i].w = (k + 3 < len) ? expf(v[i].w - mx) : 0.0f;
        sum += v[i].x + v[i].y + v[i].z + v[i].w;
    }
    #pragma unroll
    for (int o = 16; o > 0; o >>= 1)
        sum += __shfl_xor_sync(0xFFFFFFFFu, sum, o);

    const float inv = 1.0f / sum;
    #pragma unroll
    for (int i = 0; i < 8; i++) {
        v[i].x *= inv; v[i].y *= inv; v[i].z *= inv; v[i].w *= inv;
        row[i * 32 + lane] = v[i];
    }
}

extern "C" void kernel_launch(void* const* d_in, const int* in_sizes, int n_in,
                              void* d_out, int out_size)
{
    // Bind inputs by element count (all six are distinct for this problem).
    const float *query = nullptr, *keys = nullptr, *Wq = nullptr,
                *bq = nullptr, *scale = nullptr;
    const int *lens = nullptr;
    for (int i = 0; i < n_in; i++) {
        switch (in_sizes[i]) {
            case B_ * TQ * DD: query = (const float*)d_in[i]; break;  // 4194304
            case B_ * TK * DD: keys  = (const float*)d_in[i]; break;  // 8388608
            case B_:           lens  = (const int*)  d_in[i]; break;  // 16
            case DD * DD:      Wq    = (const float*)d_in[i]; break;  // 262144
            case DD:           bq    = (const float*)d_in[i]; break;  // 512
            case 1:            scale = (const float*)d_in[i]; break;  // 1
            default: break;
        }
    }

    float* qp = nullptr;
    cudaGetSymbolAddress((void**)&qp, g_qprime);  // host-side query, capture-safe

    // Output layout: (context, attn) concatenated in reference return order.
    float* context = (float*)d_out;                            // B*TQ*DD
    float* attn    = (float*)d_out + (size_t)B_ * TQ * DD;     // B*TQ*TK

    dim3 blk(NTHREADS);

    // 1) Q' = query @ Wq^T + bq   (M=B*TQ=8192, N=DD, K=DD, NT)
    gemm_kernel<true><<<dim3(DD / BN, (B_ * TQ) / BM, 1), blk>>>(
        query, DD, 0, Wq, DD, 0, qp, DD, 0, DD, bq, nullptr);

    // 2) scores = scale * Q'_b @ K_b^T  (per batch: M=TQ, N=TK, K=DD, NT)
    gemm_kernel<true><<<dim3(TK / BN, TQ / BM, B_), blk>>>(
        qp, DD, (long long)TQ * DD,
        keys, DD, (long long)TK * DD,
        attn, TK, (long long)TQ * TK,
        DD, nullptr, scale);

    // 3) masked softmax over k (writes exact zeros beyond output_lengths[b])
    softmax_kernel<<<(B_ * TQ * 32) / 128, 128>>>(attn, lens);

    // 4) context = attn @ K_b  (per batch: M=TQ, N=DD, K=TK, NN)
    gemm_kernel<false><<<dim3(DD / BN, TQ / BM, B_), blk>>>(
        attn, TK, (long long)TQ * TK,
        keys, DD, (long long)TK * DD,
        context, DD, (long long)TQ * DD,
        TK, nullptr, nullptr);
}

// round 7
// speedup vs baseline: 2.0912x; 2.0912x over previous
#include <cuda_runtime.h>
#include <cuda_bf16.h>
#include <cstdint>
#include <math.h>

#define B_   16
#define TQ   512
#define TK   1024
#define DD   512

typedef __nv_bfloat16 bf16;

// ---------------- device scratch (no allocation allowed) ----------------
__device__ bf16 g_qh [(size_t)B_*TQ*DD], g_ql [(size_t)B_*TQ*DD];   // query split
__device__ bf16 g_wh [DD*DD],            g_wl [DD*DD];              // Wq split
__device__ bf16 g_kh [(size_t)B_*TK*DD], g_kl [(size_t)B_*TK*DD];   // keys split   [B,TK,DD]
__device__ bf16 g_kth[(size_t)B_*DD*TK], g_ktl[(size_t)B_*DD*TK];   // keys^T split [B,DD,TK]
__device__ bf16 g_qph[(size_t)B_*TQ*DD], g_qpl[(size_t)B_*TQ*DD];   // Q' split
__device__ bf16 g_ah [(size_t)B_*TQ*TK], g_al [(size_t)B_*TQ*TK];   // attn split

// ---------------- helpers ----------------
__device__ __forceinline__ uint32_t smem_u32(const void* p) {
    uint32_t a;
    asm("{ .reg .u64 t; cvta.to.shared.u64 t, %1; cvt.u32.u64 %0, t; }" : "=r"(a) : "l"(p));
    return a;
}
#define SW128(o) ((o) ^ (((o) >> 3) & 0x70))

__device__ __forceinline__ void cpa16(uint32_t dst, const void* src) {
    asm volatile("cp.async.cg.shared.global [%0], [%1], 16;" :: "r"(dst), "l"(src));
}
__device__ __forceinline__ void cpa_commit() {
    asm volatile("cp.async.commit_group;" ::: "memory");
}
__device__ __forceinline__ void ldsm4(uint32_t* r, uint32_t addr) {
    asm volatile("ldmatrix.sync.aligned.m8n8.x4.shared.b16 {%0,%1,%2,%3}, [%4];"
                 : "=r"(r[0]), "=r"(r[1]), "=r"(r[2]), "=r"(r[3]) : "r"(addr));
}
__device__ __forceinline__ void mma16816(float* d, const uint32_t* a,
                                         uint32_t b0, uint32_t b1) {
    asm volatile(
        "mma.sync.aligned.m16n8k16.row.col.f32.bf16.bf16.f32 "
        "{%0,%1,%2,%3}, {%4,%5,%6,%7}, {%8,%9}, {%0,%1,%2,%3};"
        : "+f"(d[0]), "+f"(d[1]), "+f"(d[2]), "+f"(d[3])
        : "r"(a[0]), "r"(a[1]), "r"(a[2]), "r"(a[3]), "r"(b0), "r"(b1));
}

// ---------------- split kernels ----------------
__global__ void __launch_bounds__(256)
split_kernel(const float* __restrict__ x, bf16* __restrict__ hi,
             bf16* __restrict__ lo, int n4)
{
    int i = blockIdx.x * 256 + threadIdx.x;
    if (i >= n4) return;
    float4 v = ((const float4*)x)[i];
    union { bf16 b[4]; uint2 u; } H, L;
    float xs[4] = {v.x, v.y, v.z, v.w};
    #pragma unroll
    for (int j = 0; j < 4; j++) {
        bf16 h = __float2bfloat16(xs[j]);
        H.b[j] = h;
        L.b[j] = __float2bfloat16(xs[j] - __bfloat162float(h));
    }
    ((uint2*)hi)[i] = H.u;
    ((uint2*)lo)[i] = L.u;
}

// keys [B,TK,DD] -> split [B,TK,DD] AND transposed split [B,DD,TK], one read
__global__ void __launch_bounds__(256)
ksplit_kernel(const float* __restrict__ x,
              bf16* __restrict__ kh, bf16* __restrict__ kl,
              bf16* __restrict__ th, bf16* __restrict__ tl)
{
    __shared__ float t[32][33];
    int b = blockIdx.z;
    int k0 = blockIdx.x * 32, d0 = blockIdx.y * 32;
    const float* xb = x + (size_t)b * TK * DD;
    int tx = threadIdx.x & 31, ty = threadIdx.x >> 5;  // 32 x 8
    #pragma unroll
    for (int i = 0; i < 32; i += 8) {
        float v = xb[(size_t)(k0 + ty + i) * DD + d0 + tx];
        t[ty + i][tx] = v;
        bf16 h = __float2bfloat16(v);
        size_t o = (size_t)b * TK * DD + (size_t)(k0 + ty + i) * DD + d0 + tx;
        kh[o] = h;
        kl[o] = __float2bfloat16(v - __bfloat162float(h));
    }
    __syncthreads();
    #pragma unroll
    for (int i = 0; i < 32; i += 8) {
        float v = t[tx][ty + i];
        bf16 h = __float2bfloat16(v);
        size_t o = (size_t)b * DD * TK + (size_t)(d0 + ty + i) * TK + k0 + tx;
        th[o] = h;
        tl[o] = __float2bfloat16(v - __bfloat162float(h));
    }
}

// ---------------- 3-term split-bf16 HMMA NT GEMM ----------------
// C[m,n] = alpha * sum_k A[m,k]*B[n,k] (+bias[n]); A,B bf16 (hi,lo), k-contiguous.
// Tile 128x128xBK64, 256 thr, 8 warps (2m x 4n), 2-stage cp.async, SW128 smem.
// OUT_MODE 0: fp32 C. OUT_MODE 1: split-bf16 (Ch, Cl).
#define STAGE 65536          // Ah 16K | Al 16K | Bh 16K | Bl 16K
#define SMEM_DYN (2 * STAGE)

template<int OUT_MODE>
__global__ void __launch_bounds__(256)
mma_gemm(const bf16* __restrict__ Ah, const bf16* __restrict__ Al, long long sA, int lda,
         const bf16* __restrict__ Bh, const bf16* __restrict__ Bl, long long sB, int ldb,
         float* __restrict__ C, bf16* __restrict__ Ch, bf16* __restrict__ Cl,
         long long sC, int ldc, int K,
         const float* __restrict__ bias, const float* __restrict__ scale)
{
    extern __shared__ char smem[];
    const uint32_t sbase = smem_u32(smem);
    const int tid = threadIdx.x;

    Ah += (long long)blockIdx.z * sA;  Al += (long long)blockIdx.z * sA;
    Bh += (long long)blockIdx.z * sB;  Bl += (long long)blockIdx.z * sB;
    const int m0 = blockIdx.y * 128, n0 = blockIdx.x * 128;

    const bf16* pAh = Ah + (size_t)m0 * lda;
    const bf16* pAl = Al + (size_t)m0 * lda;
    const bf16* pBh = Bh + (size_t)n0 * ldb;
    const bf16* pBl = Bl + (size_t)n0 * ldb;

    const int NC = K >> 6;

    // ---- loader: 128 rows x 64 bf16 (128B rows), SW128 swizzle ----
    auto load_chunk = [&](int c, int s) {
        const uint32_t base = sbase + s * STAGE;
        const size_t ck = (size_t)c * 64;
        #pragma unroll
        for (int i = 0; i < 4; i++) {
            int u = tid + i * 256;
            int row = u >> 3, c8 = u & 7;
            uint32_t off = SW128((uint32_t)((row << 7) | (c8 << 4)));
            const size_t g = (size_t)row * lda + ck + c8 * 8;
            cpa16(base +         off, pAh + g);
            cpa16(base + 16384 + off, pAl + g);
        }
        #pragma unroll
        for (int i = 0; i < 4; i++) {
            int u = tid + i * 256;
            int row = u >> 3, c8 = u & 7;
            uint32_t off = SW128((uint32_t)((row << 7) | (c8 << 4)));
            const size_t g = (size_t)row * ldb + ck + c8 * 8;
            cpa16(base + 32768 + off, pBh + g);
            cpa16(base + 49152 + off, pBl + g);
        }
        cpa_commit();
    };

    const int lane = tid & 31;
    const int wid = tid >> 5, wm = wid >> 2, wn = wid & 3;
    const uint32_t arow = (uint32_t)(wm * 64 + (lane & 15));
    const uint32_t brow = (uint32_t)(wn * 32 + (lane & 15));
    const uint32_t chalf = (uint32_t)(lane >> 4);

    float acc[4][4][4];
    #pragma unroll
    for (int i = 0; i < 4; i++)
        #pragma unroll
        for (int j = 0; j < 4; j++)
            #pragma unroll
            for (int e = 0; e < 4; e++) acc[i][j][e] = 0.0f;

    load_chunk(0, 0);

    for (int c = 0; c < NC; c++) {
        const int s = c & 1;
        if (c + 1 < NC) {
            load_chunk(c + 1, s ^ 1);
            asm volatile("cp.async.wait_group 1;" ::: "memory");
        } else {
            asm volatile("cp.async.wait_group 0;" ::: "memory");
        }
        __syncthreads();

        const uint32_t SAh = sbase + s * STAGE;
        const uint32_t SAl = SAh + 16384;
        const uint32_t SBh = SAh + 32768;
        const uint32_t SBl = SAh + 49152;

        #pragma unroll
        for (int kt = 0; kt < 4; kt++) {
            const uint32_t ck16 = (uint32_t)((kt * 2 + chalf) << 4);
            uint32_t a_h[4][4], a_l[4][4], b_h[2][4], b_l[2][4];
            #pragma unroll
            for (int mt = 0; mt < 4; mt++) {
                uint32_t off = SW128((uint32_t)(((arow + mt * 16) << 7) | ck16));
                ldsm4(a_h[mt], SAh + off);
                ldsm4(a_l[mt], SAl + off);
            }
            #pragma unroll
            for (int ng = 0; ng < 2; ng++) {
                uint32_t off = SW128((uint32_t)(((brow + ng * 16) << 7) | ck16));
                ldsm4(b_h[ng], SBh + off);
                ldsm4(b_l[ng], SBl + off);
            }
            #pragma unroll
            for (int mt = 0; mt < 4; mt++) {
                #pragma unroll
                for (int nt = 0; nt < 4; nt++) {
                    const int ng = nt >> 1, sel = nt & 1;
                    const uint32_t bh0 = b_h[ng][sel], bh1 = b_h[ng][sel + 2];
                    const uint32_t bl0 = b_l[ng][sel], bl1 = b_l[ng][sel + 2];
                    mma16816(acc[mt][nt], a_h[mt], bh0, bh1);   // hi*hi
                    mma16816(acc[mt][nt], a_h[mt], bl0, bl1);   // hi*lo
                    mma16816(acc[mt][nt], a_l[mt], bh0, bh1);   // lo*hi
                }
            }
        }
        __syncthreads();
    }

    // ---- epilogue ----
    const float alpha = scale ? __ldg(scale) : 1.0f;
    const int mrow = m0 + wm * 64 + (lane >> 2);
    #pragma unroll
    for (int mt = 0; mt < 4; mt++) {
        #pragma unroll
        for (int nt = 0; nt < 4; nt++) {
            const int n = n0 + wn * 32 + nt * 8 + 2 * (lane & 3);
            const float bv0 = bias ? bias[n]     : 0.0f;
            const float bv1 = bias ? bias[n + 1] : 0.0f;
            #pragma unroll
            for (int h = 0; h < 2; h++) {
                const long long m = (long long)(mrow + mt * 16 + h * 8);
                const float v0 = acc[mt][nt][2 * h + 0] * alpha + bv0;
                const float v1 = acc[mt][nt][2 * h + 1] * alpha + bv1;
                const size_t idx = (size_t)blockIdx.z * sC + m * ldc + n;
                if (OUT_MODE == 0) {
                    *(float2*)(C + idx) = make_float2(v0, v1);
                } else {
                    bf16 h0 = __float2bfloat16(v0), h1 = __float2bfloat16(v1);
                    bf16 l0 = __float2bfloat16(v0 - __bfloat162float(h0));
                    bf16 l1 = __float2bfloat16(v1 - __bfloat162float(h1));
                    *(__nv_bfloat162*)(Ch + idx) = __nv_bfloat162(h0, h1);
                    *(__nv_bfloat162*)(Cl + idx) = __nv_bfloat162(l0, l1);
                }
            }
        }
    }
}

// ---------------- softmax: warp/row, masked, writes fp32 + split bf16 ----------------
__global__ void __launch_bounds__(128)
softmax_kernel(float* __restrict__ attn, const int* __restrict__ lens,
               bf16* __restrict__ ah, bf16* __restrict__ al)
{
    int warp = (int)((blockIdx.x * blockDim.x + threadIdx.x) >> 5);
    int lane = threadIdx.x & 31;
    if (warp >= B_ * TQ) return;
    const int len = lens[warp / TQ];
    float4* row = (float4*)(attn + (size_t)warp * TK);

    float4 v[8];
    float mx = -INFINITY;
    #pragma unroll
    for (int i = 0; i < 8; i++) {
        v[i] = row[i * 32 + lane];
        int k = 4 * (i * 32 + lane);
        if (k + 0 < len) mx = fmaxf(mx, v[i].x);
        if (k + 1 < len) mx = fmaxf(mx, v[i].y);
        if (k + 2 < len) mx = fmaxf(mx, v[i].z);
        if (k + 3 < len) mx = fmaxf(mx, v[i].w);
    }
    #pragma unroll
    for (int o = 16; o > 0; o >>= 1)
        mx = fmaxf(mx, __shfl_xor_sync(0xFFFFFFFFu, mx, o));

    float sum = 0.0f;
    #pragma unroll
    for (int i = 0; i < 8; i++) {
        int k = 4 * (i * 32 + lane);
        v[i].x = (k + 0 < len) ? expf(v[i].x - mx) : 0.0f;
        v[i].y = (k + 1 < len) ? expf(v[i].y - mx) : 0.0f;
        v[i].z = (k + 2 < len) ? expf(v[i].z - mx) : 0.0f;
        v[i].w = (k + 3 < len) ? expf(v[i].w - mx) : 0.0f;
        sum += v[i].x + v[i].y + v[i].z + v[i].w;
    }
    #pragma unroll
    for (int o = 16; o > 0; o >>= 1)
        sum += __shfl_xor_sync(0xFFFFFFFFu, sum, o);

    const float inv = 1.0f / sum;
    uint2* rh = (uint2*)(ah + (size_t)warp * TK);
    uint2* rl = (uint2*)(al + (size_t)warp * TK);
    #pragma unroll
    for (int i = 0; i < 8; i++) {
        v[i].x *= inv; v[i].y *= inv; v[i].z *= inv; v[i].w *= inv;
        row[i * 32 + lane] = v[i];
        union { bf16 b[4]; uint2 u; } H, L;
        float xs[4] = {v[i].x, v[i].y, v[i].z, v[i].w};
        #pragma unroll
        for (int j = 0; j < 4; j++) {
            bf16 h = __float2bfloat16(xs[j]);
            H.b[j] = h;
            L.b[j] = __float2bfloat16(xs[j] - __bfloat162float(h));
        }
        rh[i * 32 + lane] = H.u;
        rl[i * 32 + lane] = L.u;
    }
}

// ---------------- launch ----------------
extern "C" void kernel_launch(void* const* d_in, const int* in_sizes, int n_in,
                              void* d_out, int out_size)
{
    const float *query = nullptr, *keys = nullptr, *Wq = nullptr,
                *bq = nullptr, *scale = nullptr;
    const int *lens = nullptr;
    for (int i = 0; i < n_in; i++) {
        switch (in_sizes[i]) {
            case B_ * TQ * DD: query = (const float*)d_in[i]; break;
            case B_ * TK * DD: keys  = (const float*)d_in[i]; break;
            case B_:           lens  = (const int*)  d_in[i]; break;
            case DD * DD:      Wq    = (const float*)d_in[i]; break;
            case DD:           bq    = (const float*)d_in[i]; break;
            case 1:            scale = (const float*)d_in[i]; break;
            default: break;
        }
    }

    bf16 *qh, *ql, *wh, *wl, *kh, *kl, *kth, *ktl, *qph, *qpl, *ah, *al;
    cudaGetSymbolAddress((void**)&qh,  g_qh);  cudaGetSymbolAddress((void**)&ql,  g_ql);
    cudaGetSymbolAddress((void**)&wh,  g_wh);  cudaGetSymbolAddress((void**)&wl,  g_wl);
    cudaGetSymbolAddress((void**)&kh,  g_kh);  cudaGetSymbolAddress((void**)&kl,  g_kl);
    cudaGetSymbolAddress((void**)&kth, g_kth); cudaGetSymbolAddress((void**)&ktl, g_ktl);
    cudaGetSymbolAddress((void**)&qph, g_qph); cudaGetSymbolAddress((void**)&qpl, g_qpl);
    cudaGetSymbolAddress((void**)&ah,  g_ah);  cudaGetSymbolAddress((void**)&al,  g_al);

    cudaFuncSetAttribute(mma_gemm<0>, cudaFuncAttributeMaxDynamicSharedMemorySize, SMEM_DYN);
    cudaFuncSetAttribute(mma_gemm<1>, cudaFuncAttributeMaxDynamicSharedMemorySize, SMEM_DYN);

    float* context = (float*)d_out;                         // B*TQ*DD
    float* attn    = (float*)d_out + (size_t)B_ * TQ * DD;  // B*TQ*TK

    // input splits
    split_kernel<<<(B_ * TQ * DD / 4 + 255) / 256, 256>>>(query, qh, ql, B_ * TQ * DD / 4);
    split_kernel<<<(DD * DD / 4 + 255) / 256, 256>>>(Wq, wh, wl, DD * DD / 4);
    ksplit_kernel<<<dim3(TK / 32, DD / 32, B_), 256>>>(keys, kh, kl, kth, ktl);

    // 1) Q' = query @ Wq^T + bq -> split bf16 directly (M=8192, N=512, K=512)
    mma_gemm<1><<<dim3(DD / 128, (B_ * TQ) / 128, 1), 256, SMEM_DYN>>>(
        qh, ql, 0, DD, wh, wl, 0, DD,
        nullptr, qph, qpl, 0, DD, DD, bq, nullptr);

    // 2) scores = scale * Q'_b @ K_b^T -> fp32 attn (per batch M=512, N=1024, K=512)
    mma_gemm<0><<<dim3(TK / 128, TQ / 128, B_), 256, SMEM_DYN>>>(
        qph, qpl, (long long)TQ * DD, DD,
        kh, kl, (long long)TK * DD, DD,
        attn, nullptr, nullptr, (long long)TQ * TK, TK, DD, nullptr, scale);

    // 3) masked softmax (fp32 out + fused split)
    softmax_kernel<<<(B_ * TQ * 32) / 128, 128>>>(attn, lens, ah, al);

    // 4) context = attn_b @ keysT_b^T -> fp32 (per batch M=512, N=512, K=1024)
    mma_gemm<0><<<dim3(DD / 128, TQ / 128, B_), 256, SMEM_DYN>>>(
        ah, al, (long long)TQ * TK, TK,
        kth, ktl, (long long)DD * TK, TK,
        context, nullptr, nullptr, (long long)TQ * DD, DD, TK, nullptr, nullptr);
}

// round 8
// speedup vs baseline: 2.4238x; 1.1591x over previous
#include <cuda_runtime.h>
#include <cuda_bf16.h>
#include <cstdint>
#include <math.h>

#define B_   16
#define TQ   512
#define TK   1024
#define DD   512

typedef __nv_bfloat16 bf16;

// ---------------- device scratch (no allocation allowed) ----------------
__device__ bf16 g_qh [(size_t)B_*TQ*DD], g_ql [(size_t)B_*TQ*DD];   // query split
__device__ bf16 g_wh [DD*DD],            g_wl [DD*DD];              // Wq split
__device__ bf16 g_kh [(size_t)B_*TK*DD], g_kl [(size_t)B_*TK*DD];   // keys split   [B,TK,DD]
__device__ bf16 g_kth[(size_t)B_*DD*TK], g_ktl[(size_t)B_*DD*TK];   // keys^T split [B,DD,TK]
__device__ bf16 g_qph[(size_t)B_*TQ*DD], g_qpl[(size_t)B_*TQ*DD];   // Q' split
__device__ bf16 g_ah [(size_t)B_*TQ*TK], g_al [(size_t)B_*TQ*TK];   // attn split

// ---------------- helpers ----------------
__device__ __forceinline__ uint32_t smem_u32(const void* p) {
    uint32_t a;
    asm("{ .reg .u64 t; cvta.to.shared.u64 t, %1; cvt.u32.u64 %0, t; }" : "=r"(a) : "l"(p));
    return a;
}
#define SW128(o) ((o) ^ (((o) >> 3) & 0x70))

__device__ __forceinline__ void cpa16(uint32_t dst, const void* src) {
    asm volatile("cp.async.cg.shared.global [%0], [%1], 16;" :: "r"(dst), "l"(src));
}
__device__ __forceinline__ void cpa_commit() {
    asm volatile("cp.async.commit_group;" ::: "memory");
}
__device__ __forceinline__ void ldsm4(uint32_t* r, uint32_t addr) {
    asm volatile("ldmatrix.sync.aligned.m8n8.x4.shared.b16 {%0,%1,%2,%3}, [%4];"
                 : "=r"(r[0]), "=r"(r[1]), "=r"(r[2]), "=r"(r[3]) : "r"(addr));
}
__device__ __forceinline__ void mma16816(float* d, const uint32_t* a,
                                         uint32_t b0, uint32_t b1) {
    asm volatile(
        "mma.sync.aligned.m16n8k16.row.col.f32.bf16.bf16.f32 "
        "{%0,%1,%2,%3}, {%4,%5,%6,%7}, {%8,%9}, {%0,%1,%2,%3};"
        : "+f"(d[0]), "+f"(d[1]), "+f"(d[2]), "+f"(d[3])
        : "r"(a[0]), "r"(a[1]), "r"(a[2]), "r"(a[3]), "r"(b0), "r"(b1));
}

// ---------------- split kernels ----------------
__global__ void __launch_bounds__(256)
split_kernel(const float* __restrict__ x, bf16* __restrict__ hi,
             bf16* __restrict__ lo, int n4)
{
    int i = blockIdx.x * 256 + threadIdx.x;
    if (i >= n4) return;
    float4 v = ((const float4*)x)[i];
    union { bf16 b[4]; uint2 u; } H, L;
    float xs[4] = {v.x, v.y, v.z, v.w};
    #pragma unroll
    for (int j = 0; j < 4; j++) {
        bf16 h = __float2bfloat16(xs[j]);
        H.b[j] = h;
        L.b[j] = __float2bfloat16(xs[j] - __bfloat162float(h));
    }
    ((uint2*)hi)[i] = H.u;
    ((uint2*)lo)[i] = L.u;
}

// keys [B,TK,DD] -> split [B,TK,DD] AND transposed split [B,DD,TK], one read
__global__ void __launch_bounds__(256)
ksplit_kernel(const float* __restrict__ x,
              bf16* __restrict__ kh, bf16* __restrict__ kl,
              bf16* __restrict__ th, bf16* __restrict__ tl)
{
    __shared__ float t[32][33];
    int b = blockIdx.z;
    int k0 = blockIdx.x * 32, d0 = blockIdx.y * 32;
    const float* xb = x + (size_t)b * TK * DD;
    int tx = threadIdx.x & 31, ty = threadIdx.x >> 5;  // 32 x 8
    #pragma unroll
    for (int i = 0; i < 32; i += 8) {
        float v = xb[(size_t)(k0 + ty + i) * DD + d0 + tx];
        t[ty + i][tx] = v;
        bf16 h = __float2bfloat16(v);
        size_t o = (size_t)b * TK * DD + (size_t)(k0 + ty + i) * DD + d0 + tx;
        kh[o] = h;
        kl[o] = __float2bfloat16(v - __bfloat162float(h));
    }
    __syncthreads();
    #pragma unroll
    for (int i = 0; i < 32; i += 8) {
        float v = t[tx][ty + i];
        bf16 h = __float2bfloat16(v);
        size_t o = (size_t)b * DD * TK + (size_t)(d0 + ty + i) * TK + k0 + tx;
        th[o] = h;
        tl[o] = __float2bfloat16(v - __bfloat162float(h));
    }
}

// ---------------- 3-term split-bf16 HMMA NT GEMM ----------------
// C[m,n] = alpha * sum_k A[m,k]*B[n,k] (+bias[n]); A,B bf16 (hi,lo), k-contiguous.
// Tile 128x64xBK64, 256 thr, 8 warps (4m x 2n, warp tile 32x32),
// 2-stage cp.async, SW128 smem, 2 CTAs/SM.
// OUT_MODE 0: fp32 C. OUT_MODE 1: split-bf16 (Ch, Cl).
#define STAGE 49152          // Ah 16K | Al 16K | Bh 8K | Bl 8K
#define SMEM_DYN (2 * STAGE)

template<int OUT_MODE>
__global__ void __launch_bounds__(256, 2)
mma_gemm(const bf16* __restrict__ Ah, const bf16* __restrict__ Al, long long sA, int lda,
         const bf16* __restrict__ Bh, const bf16* __restrict__ Bl, long long sB, int ldb,
         float* __restrict__ C, bf16* __restrict__ Ch, bf16* __restrict__ Cl,
         long long sC, int ldc, int K,
         const float* __restrict__ bias, const float* __restrict__ scale)
{
    extern __shared__ char smem[];
    const uint32_t sbase = smem_u32(smem);
    const int tid = threadIdx.x;

    Ah += (long long)blockIdx.z * sA;  Al += (long long)blockIdx.z * sA;
    Bh += (long long)blockIdx.z * sB;  Bl += (long long)blockIdx.z * sB;
    const int m0 = blockIdx.y * 128, n0 = blockIdx.x * 64;

    const bf16* pAh = Ah + (size_t)m0 * lda;
    const bf16* pAl = Al + (size_t)m0 * lda;
    const bf16* pBh = Bh + (size_t)n0 * ldb;
    const bf16* pBl = Bl + (size_t)n0 * ldb;

    const int NC = K >> 6;

    // ---- loader: rows x 64 bf16 (128B rows), SW128 swizzle ----
    auto load_chunk = [&](int c, int s) {
        const uint32_t base = sbase + s * STAGE;
        const size_t ck = (size_t)c * 64;
        #pragma unroll
        for (int i = 0; i < 4; i++) {              // A: 128 rows x 8 units
            int u = tid + i * 256;
            int row = u >> 3, c8 = u & 7;
            uint32_t off = SW128((uint32_t)((row << 7) | (c8 << 4)));
            const size_t g = (size_t)row * lda + ck + c8 * 8;
            cpa16(base +         off, pAh + g);
            cpa16(base + 16384 + off, pAl + g);
        }
        #pragma unroll
        for (int i = 0; i < 2; i++) {              // B: 64 rows x 8 units
            int u = tid + i * 256;
            int row = u >> 3, c8 = u & 7;
            uint32_t off = SW128((uint32_t)((row << 7) | (c8 << 4)));
            const size_t g = (size_t)row * ldb + ck + c8 * 8;
            cpa16(base + 32768 + off, pBh + g);
            cpa16(base + 40960 + off, pBl + g);
        }
        cpa_commit();
    };

    const int lane = tid & 31;
    const int wid = tid >> 5, wm = wid >> 1, wn = wid & 1;   // 4m x 2n
    const uint32_t arow = (uint32_t)(wm * 32 + (lane & 15));
    const uint32_t brow = (uint32_t)(wn * 32 + (lane & 15));
    const uint32_t chalf = (uint32_t)(lane >> 4);

    float acc[2][4][4];
    #pragma unroll
    for (int i = 0; i < 2; i++)
        #pragma unroll
        for (int j = 0; j < 4; j++)
            #pragma unroll
            for (int e = 0; e < 4; e++) acc[i][j][e] = 0.0f;

    load_chunk(0, 0);

    for (int c = 0; c < NC; c++) {
        const int s = c & 1;
        if (c + 1 < NC) {
            load_chunk(c + 1, s ^ 1);
            asm volatile("cp.async.wait_group 1;" ::: "memory");
        } else {
            asm volatile("cp.async.wait_group 0;" ::: "memory");
        }
        __syncthreads();

        const uint32_t SAh = sbase + s * STAGE;
        const uint32_t SAl = SAh + 16384;
        const uint32_t SBh = SAh + 32768;
        const uint32_t SBl = SAh + 40960;

        #pragma unroll
        for (int kt = 0; kt < 4; kt++) {
            const uint32_t ck16 = (uint32_t)((kt * 2 + chalf) << 4);
            uint32_t a_h[2][4], a_l[2][4], b_h[2][4], b_l[2][4];
            #pragma unroll
            for (int mt = 0; mt < 2; mt++) {
                uint32_t off = SW128((uint32_t)(((arow + mt * 16) << 7) | ck16));
                ldsm4(a_h[mt], SAh + off);
                ldsm4(a_l[mt], SAl + off);
            }
            #pragma unroll
            for (int ng = 0; ng < 2; ng++) {
                uint32_t off = SW128((uint32_t)(((brow + ng * 16) << 7) | ck16));
                ldsm4(b_h[ng], SBh + off);
                ldsm4(b_l[ng], SBl + off);
            }
            // term-outer ordering: same-acc MMAs are 8 issues apart
            #pragma unroll
            for (int mt = 0; mt < 2; mt++)
                #pragma unroll
                for (int nt = 0; nt < 4; nt++) {
                    const int ng = nt >> 1, sel = nt & 1;
                    mma16816(acc[mt][nt], a_h[mt], b_h[ng][sel], b_h[ng][sel + 2]);
                }
            #pragma unroll
            for (int mt = 0; mt < 2; mt++)
                #pragma unroll
                for (int nt = 0; nt < 4; nt++) {
                    const int ng = nt >> 1, sel = nt & 1;
                    mma16816(acc[mt][nt], a_h[mt], b_l[ng][sel], b_l[ng][sel + 2]);
                }
            #pragma unroll
            for (int mt = 0; mt < 2; mt++)
                #pragma unroll
                for (int nt = 0; nt < 4; nt++) {
                    const int ng = nt >> 1, sel = nt & 1;
                    mma16816(acc[mt][nt], a_l[mt], b_h[ng][sel], b_h[ng][sel + 2]);
                }
        }
        __syncthreads();
    }

    // ---- epilogue ----
    const float alpha = scale ? __ldg(scale) : 1.0f;
    const int mrow = m0 + wm * 32 + (lane >> 2);
    #pragma unroll
    for (int mt = 0; mt < 2; mt++) {
        #pragma unroll
        for (int nt = 0; nt < 4; nt++) {
            const int n = n0 + wn * 32 + nt * 8 + 2 * (lane & 3);
            const float bv0 = bias ? bias[n]     : 0.0f;
            const float bv1 = bias ? bias[n + 1] : 0.0f;
            #pragma unroll
            for (int h = 0; h < 2; h++) {
                const long long m = (long long)(mrow + mt * 16 + h * 8);
                const float v0 = acc[mt][nt][2 * h + 0] * alpha + bv0;
                const float v1 = acc[mt][nt][2 * h + 1] * alpha + bv1;
                const size_t idx = (size_t)blockIdx.z * sC + m * ldc + n;
                if (OUT_MODE == 0) {
                    *(float2*)(C + idx) = make_float2(v0, v1);
                } else {
                    bf16 h0 = __float2bfloat16(v0), h1 = __float2bfloat16(v1);
                    bf16 l0 = __float2bfloat16(v0 - __bfloat162float(h0));
                    bf16 l1 = __float2bfloat16(v1 - __bfloat162float(h1));
                    *(__nv_bfloat162*)(Ch + idx) = __nv_bfloat162(h0, h1);
                    *(__nv_bfloat162*)(Cl + idx) = __nv_bfloat162(l0, l1);
                }
            }
        }
    }
}

// ---------------- softmax: warp/row, masked, writes fp32 + split bf16 ----------------
__global__ void __launch_bounds__(128)
softmax_kernel(float* __restrict__ attn, const int* __restrict__ lens,
               bf16* __restrict__ ah, bf16* __restrict__ al)
{
    int warp = (int)((blockIdx.x * blockDim.x + threadIdx.x) >> 5);
    int lane = threadIdx.x & 31;
    if (warp >= B_ * TQ) return;
    const int len = lens[warp / TQ];
    float4* row = (float4*)(attn + (size_t)warp * TK);

    float4 v[8];
    float mx = -INFINITY;
    #pragma unroll
    for (int i = 0; i < 8; i++) {
        v[i] = row[i * 32 + lane];
        int k = 4 * (i * 32 + lane);
        if (k + 0 < len) mx = fmaxf(mx, v[i].x);
        if (k + 1 < len) mx = fmaxf(mx, v[i].y);
        if (k + 2 < len) mx = fmaxf(mx, v[i].z);
        if (k + 3 < len) mx = fmaxf(mx, v[i].w);
    }
    #pragma unroll
    for (int o = 16; o > 0; o >>= 1)
        mx = fmaxf(mx, __shfl_xor_sync(0xFFFFFFFFu, mx, o));

    float sum = 0.0f;
    #pragma unroll
    for (int i = 0; i < 8; i++) {
        int k = 4 * (i * 32 + lane);
        v[i].x = (k + 0 < len) ? expf(v[i].x - mx) : 0.0f;
        v[i].y = (k + 1 < len) ? expf(v[i].y - mx) : 0.0f;
        v[i].z = (k + 2 < len) ? expf(v[i].z - mx) : 0.0f;
        v[i].w = (k + 3 < len) ? expf(v[i].w - mx) : 0.0f;
        sum += v[i].x + v[i].y + v[i].z + v[i].w;
    }
    #pragma unroll
    for (int o = 16; o > 0; o >>= 1)
        sum += __shfl_xor_sync(0xFFFFFFFFu, sum, o);

    const float inv = 1.0f / sum;
    uint2* rh = (uint2*)(ah + (size_t)warp * TK);
    uint2* rl = (uint2*)(al + (size_t)warp * TK);
    #pragma unroll
    for (int i = 0; i < 8; i++) {
        v[i].x *= inv; v[i].y *= inv; v[i].z *= inv; v[i].w *= inv;
        row[i * 32 + lane] = v[i];
        union { bf16 b[4]; uint2 u; } H, L;
        float xs[4] = {v[i].x, v[i].y, v[i].z, v[i].w};
        #pragma unroll
        for (int j = 0; j < 4; j++) {
            bf16 h = __float2bfloat16(xs[j]);
            H.b[j] = h;
            L.b[j] = __float2bfloat16(xs[j] - __bfloat162float(h));
        }
        rh[i * 32 + lane] = H.u;
        rl[i * 32 + lane] = L.u;
    }
}

// ---------------- launch ----------------
extern "C" void kernel_launch(void* const* d_in, const int* in_sizes, int n_in,
                              void* d_out, int out_size)
{
    const float *query = nullptr, *keys = nullptr, *Wq = nullptr,
                *bq = nullptr, *scale = nullptr;
    const int *lens = nullptr;
    for (int i = 0; i < n_in; i++) {
        switch (in_sizes[i]) {
            case B_ * TQ * DD: query = (const float*)d_in[i]; break;
            case B_ * TK * DD: keys  = (const float*)d_in[i]; break;
            case B_:           lens  = (const int*)  d_in[i]; break;
            case DD * DD:      Wq    = (const float*)d_in[i]; break;
            case DD:           bq    = (const float*)d_in[i]; break;
            case 1:            scale = (const float*)d_in[i]; break;
            default: break;
        }
    }

    bf16 *qh, *ql, *wh, *wl, *kh, *kl, *kth, *ktl, *qph, *qpl, *ah, *al;
    cudaGetSymbolAddress((void**)&qh,  g_qh);  cudaGetSymbolAddress((void**)&ql,  g_ql);
    cudaGetSymbolAddress((void**)&wh,  g_wh);  cudaGetSymbolAddress((void**)&wl,  g_wl);
    cudaGetSymbolAddress((void**)&kh,  g_kh);  cudaGetSymbolAddress((void**)&kl,  g_kl);
    cudaGetSymbolAddress((void**)&kth, g_kth); cudaGetSymbolAddress((void**)&ktl, g_ktl);
    cudaGetSymbolAddress((void**)&qph, g_qph); cudaGetSymbolAddress((void**)&qpl, g_qpl);
    cudaGetSymbolAddress((void**)&ah,  g_ah);  cudaGetSymbolAddress((void**)&al,  g_al);

    cudaFuncSetAttribute(mma_gemm<0>, cudaFuncAttributeMaxDynamicSharedMemorySize, SMEM_DYN);
    cudaFuncSetAttribute(mma_gemm<1>, cudaFuncAttributeMaxDynamicSharedMemorySize, SMEM_DYN);

    float* context = (float*)d_out;                         // B*TQ*DD
    float* attn    = (float*)d_out + (size_t)B_ * TQ * DD;  // B*TQ*TK

    // input splits
    split_kernel<<<(B_ * TQ * DD / 4 + 255) / 256, 256>>>(query, qh, ql, B_ * TQ * DD / 4);
    split_kernel<<<(DD * DD / 4 + 255) / 256, 256>>>(Wq, wh, wl, DD * DD / 4);
    ksplit_kernel<<<dim3(TK / 32, DD / 32, B_), 256>>>(keys, kh, kl, kth, ktl);

    // 1) Q' = query @ Wq^T + bq -> split bf16 directly (M=8192, N=512, K=512)
    mma_gemm<1><<<dim3(DD / 64, (B_ * TQ) / 128, 1), 256, SMEM_DYN>>>(
        qh, ql, 0, DD, wh, wl, 0, DD,
        nullptr, qph, qpl, 0, DD, DD, bq, nullptr);

    // 2) scores = scale * Q'_b @ K_b^T -> fp32 attn (per batch M=512, N=1024, K=512)
    mma_gemm<0><<<dim3(TK / 64, TQ / 128, B_), 256, SMEM_DYN>>>(
        qph, qpl, (long long)TQ * DD, DD,
        kh, kl, (long long)TK * DD, DD,
        attn, nullptr, nullptr, (long long)TQ * TK, TK, DD, nullptr, scale);

    // 3) masked softmax (fp32 out + fused split)
    softmax_kernel<<<(B_ * TQ * 32) / 128, 128>>>(attn, lens, ah, al);

    // 4) context = attn_b @ keysT_b^T -> fp32 (per batch M=512, N=512, K=1024)
    mma_gemm<0><<<dim3(DD / 64, TQ / 128, B_), 256, SMEM_DYN>>>(
        ah, al, (long long)TQ * TK, TK,
        kth, ktl, (long long)DD * TK, TK,
        context, nullptr, nullptr, (long long)TQ * DD, DD, TK, nullptr, nullptr);
}

// round 9
// speedup vs baseline: 2.7383x; 1.1298x over previous
#include <cuda_runtime.h>
#include <cuda_bf16.h>
#include <cstdint>
#include <math.h>

#define B_   16
#define TQ   512
#define TK   1024
#define DD   512

typedef __nv_bfloat16 bf16;

// ---------------- device scratch (no allocation allowed) ----------------
__device__ bf16 g_qh [(size_t)B_*TQ*DD], g_ql [(size_t)B_*TQ*DD];   // query split
__device__ bf16 g_wh [DD*DD],            g_wl [DD*DD];              // Wq split
__device__ bf16 g_kh [(size_t)B_*TK*DD], g_kl [(size_t)B_*TK*DD];   // keys split   [B,TK,DD]
__device__ bf16 g_kth[(size_t)B_*DD*TK], g_ktl[(size_t)B_*DD*TK];   // keys^T split [B,DD,TK]
__device__ bf16 g_qph[(size_t)B_*TQ*DD], g_qpl[(size_t)B_*TQ*DD];   // Q' split
__device__ bf16 g_ah [(size_t)B_*TQ*TK], g_al [(size_t)B_*TQ*TK];   // attn split

// ---------------- helpers ----------------
__device__ __forceinline__ uint32_t smem_u32(const void* p) {
    uint32_t a;
    asm("{ .reg .u64 t; cvta.to.shared.u64 t, %1; cvt.u32.u64 %0, t; }" : "=r"(a) : "l"(p));
    return a;
}
#define SW128(o) ((o) ^ (((o) >> 3) & 0x70))

__device__ __forceinline__ void cpa16(uint32_t dst, const void* src) {
    asm volatile("cp.async.cg.shared.global [%0], [%1], 16;" :: "r"(dst), "l"(src));
}
__device__ __forceinline__ void cpa_commit() {
    asm volatile("cp.async.commit_group;" ::: "memory");
}
__device__ __forceinline__ void ldsm4(uint32_t* r, uint32_t addr) {
    asm volatile("ldmatrix.sync.aligned.m8n8.x4.shared.b16 {%0,%1,%2,%3}, [%4];"
                 : "=r"(r[0]), "=r"(r[1]), "=r"(r[2]), "=r"(r[3]) : "r"(addr));
}
__device__ __forceinline__ void mma16816(float* d, const uint32_t* a,
                                         uint32_t b0, uint32_t b1) {
    asm volatile(
        "mma.sync.aligned.m16n8k16.row.col.f32.bf16.bf16.f32 "
        "{%0,%1,%2,%3}, {%4,%5,%6,%7}, {%8,%9}, {%0,%1,%2,%3};"
        : "+f"(d[0]), "+f"(d[1]), "+f"(d[2]), "+f"(d[3])
        : "r"(a[0]), "r"(a[1]), "r"(a[2]), "r"(a[3]), "r"(b0), "r"(b1));
}

// ---------------- split kernels ----------------
__global__ void __launch_bounds__(256)
split_kernel(const float* __restrict__ x, bf16* __restrict__ hi,
             bf16* __restrict__ lo, int n4)
{
    int i = blockIdx.x * 256 + threadIdx.x;
    if (i >= n4) return;
    float4 v = ((const float4*)x)[i];
    union { bf16 b[4]; uint2 u; } H, L;
    float xs[4] = {v.x, v.y, v.z, v.w};
    #pragma unroll
    for (int j = 0; j < 4; j++) {
        bf16 h = __float2bfloat16(xs[j]);
        H.b[j] = h;
        L.b[j] = __float2bfloat16(xs[j] - __bfloat162float(h));
    }
    ((uint2*)hi)[i] = H.u;
    ((uint2*)lo)[i] = L.u;
}

// keys [B,TK,DD] -> split [B,TK,DD] AND transposed split [B,DD,TK], one read
__global__ void __launch_bounds__(256)
ksplit_kernel(const float* __restrict__ x,
              bf16* __restrict__ kh, bf16* __restrict__ kl,
              bf16* __restrict__ th, bf16* __restrict__ tl)
{
    __shared__ float t[32][33];
    int b = blockIdx.z;
    int k0 = blockIdx.x * 32, d0 = blockIdx.y * 32;
    const float* xb = x + (size_t)b * TK * DD;
    int tx = threadIdx.x & 31, ty = threadIdx.x >> 5;  // 32 x 8
    #pragma unroll
    for (int i = 0; i < 32; i += 8) {
        float v = xb[(size_t)(k0 + ty + i) * DD + d0 + tx];
        t[ty + i][tx] = v;
        bf16 h = __float2bfloat16(v);
        size_t o = (size_t)b * TK * DD + (size_t)(k0 + ty + i) * DD + d0 + tx;
        kh[o] = h;
        kl[o] = __float2bfloat16(v - __bfloat162float(h));
    }
    __syncthreads();
    #pragma unroll
    for (int i = 0; i < 32; i += 8) {
        float v = t[tx][ty + i];
        bf16 h = __float2bfloat16(v);
        size_t o = (size_t)b * DD * TK + (size_t)(d0 + ty + i) * TK + k0 + tx;
        th[o] = h;
        tl[o] = __float2bfloat16(v - __bfloat162float(h));
    }
}

// ---------------- 3-term split-bf16 HMMA NT GEMM ----------------
// C[m,n] = alpha * sum_k A[m,k]*B[n,k] (+bias[n]); A,B bf16 (hi,lo), k-contiguous.
// Tile 128x64xBK64, 256 thr, 8 warps (4m x 2n, warp tile 32x32),
// 2-stage cp.async, SW128 smem, 2 CTAs/SM, fragment double-buffer over k-steps.
// OUT_MODE 0: fp32 C. OUT_MODE 1: split-bf16 (Ch, Cl).
// LEN_MODE 0: none. 1: skip CTA if n0 >= len[z] (masked-out scores).
//           2: truncate K to ceil(len[z]/64)*64 (attn cols beyond len are 0).
#define STAGE 49152          // Ah 16K | Al 16K | Bh 8K | Bl 8K
#define SMEM_DYN (2 * STAGE)

template<int OUT_MODE, int LEN_MODE>
__global__ void __launch_bounds__(256, 2)
mma_gemm(const bf16* __restrict__ Ah, const bf16* __restrict__ Al, long long sA, int lda,
         const bf16* __restrict__ Bh, const bf16* __restrict__ Bl, long long sB, int ldb,
         float* __restrict__ C, bf16* __restrict__ Ch, bf16* __restrict__ Cl,
         long long sC, int ldc, int K,
         const float* __restrict__ bias, const float* __restrict__ scale,
         const int* __restrict__ lens)
{
    extern __shared__ char smem[];
    const uint32_t sbase = smem_u32(smem);
    const int tid = threadIdx.x;

    const int m0 = blockIdx.y * 128, n0 = blockIdx.x * 64;

    if (LEN_MODE == 1) {
        if (n0 >= lens[blockIdx.z]) return;   // softmax zeros+overwrites this region
    }
    int Keff = K;
    if (LEN_MODE == 2) {
        Keff = (lens[blockIdx.z] + 63) & ~63; // attn == 0 beyond len: skip chunks
    }

    Ah += (long long)blockIdx.z * sA;  Al += (long long)blockIdx.z * sA;
    Bh += (long long)blockIdx.z * sB;  Bl += (long long)blockIdx.z * sB;

    const bf16* pAh = Ah + (size_t)m0 * lda;
    const bf16* pAl = Al + (size_t)m0 * lda;
    const bf16* pBh = Bh + (size_t)n0 * ldb;
    const bf16* pBl = Bl + (size_t)n0 * ldb;

    const int NC = Keff >> 6;

    // ---- loader: rows x 64 bf16 (128B rows), SW128 swizzle ----
    auto load_chunk = [&](int c, int s) {
        const uint32_t base = sbase + s * STAGE;
        const size_t ck = (size_t)c * 64;
        #pragma unroll
        for (int i = 0; i < 4; i++) {              // A: 128 rows x 8 units
            int u = tid + i * 256;
            int row = u >> 3, c8 = u & 7;
            uint32_t off = SW128((uint32_t)((row << 7) | (c8 << 4)));
            const size_t g = (size_t)row * lda + ck + c8 * 8;
            cpa16(base +         off, pAh + g);
            cpa16(base + 16384 + off, pAl + g);
        }
        #pragma unroll
        for (int i = 0; i < 2; i++) {              // B: 64 rows x 8 units
            int u = tid + i * 256;
            int row = u >> 3, c8 = u & 7;
            uint32_t off = SW128((uint32_t)((row << 7) | (c8 << 4)));
            const size_t g = (size_t)row * ldb + ck + c8 * 8;
            cpa16(base + 32768 + off, pBh + g);
            cpa16(base + 40960 + off, pBl + g);
        }
        cpa_commit();
    };

    const int lane = tid & 31;
    const int wid = tid >> 5, wm = wid >> 1, wn = wid & 1;   // 4m x 2n
    const uint32_t arow = (uint32_t)(wm * 32 + (lane & 15));
    const uint32_t brow = (uint32_t)(wn * 32 + (lane & 15));
    const uint32_t chalf = (uint32_t)(lane >> 4);

    float acc[2][4][4];
    #pragma unroll
    for (int i = 0; i < 2; i++)
        #pragma unroll
        for (int j = 0; j < 4; j++)
            #pragma unroll
            for (int e = 0; e < 4; e++) acc[i][j][e] = 0.0f;

    // fragment double buffers over k-steps
    uint32_t a_h[2][2][4], a_l[2][2][4], b_h[2][2][4], b_l[2][2][4];

    auto load_frags = [&](uint32_t SAh, uint32_t SAl, uint32_t SBh, uint32_t SBl,
                          int kt, int p) {
        const uint32_t ck16 = (uint32_t)((kt * 2 + chalf) << 4);
        #pragma unroll
        for (int mt = 0; mt < 2; mt++) {
            uint32_t off = SW128((uint32_t)(((arow + mt * 16) << 7) | ck16));
            ldsm4(a_h[p][mt], SAh + off);
            ldsm4(a_l[p][mt], SAl + off);
        }
        #pragma unroll
        for (int ng = 0; ng < 2; ng++) {
            uint32_t off = SW128((uint32_t)(((brow + ng * 16) << 7) | ck16));
            ldsm4(b_h[p][ng], SBh + off);
            ldsm4(b_l[p][ng], SBl + off);
        }
    };

    load_chunk(0, 0);

    for (int c = 0; c < NC; c++) {
        const int s = c & 1;
        if (c + 1 < NC) {
            load_chunk(c + 1, s ^ 1);
            asm volatile("cp.async.wait_group 1;" ::: "memory");
        } else {
            asm volatile("cp.async.wait_group 0;" ::: "memory");
        }
        __syncthreads();

        const uint32_t SAh = sbase + s * STAGE;
        const uint32_t SAl = SAh + 16384;
        const uint32_t SBh = SAh + 32768;
        const uint32_t SBl = SAh + 40960;

        load_frags(SAh, SAl, SBh, SBl, 0, 0);
        #pragma unroll
        for (int kt = 0; kt < 4; kt++) {
            const int cur = kt & 1;
            if (kt < 3) load_frags(SAh, SAl, SBh, SBl, kt + 1, cur ^ 1);
            // term-outer ordering: same-acc MMAs are 8 issues apart
            #pragma unroll
            for (int mt = 0; mt < 2; mt++)
                #pragma unroll
                for (int nt = 0; nt < 4; nt++) {
                    const int ng = nt >> 1, sel = nt & 1;
                    mma16816(acc[mt][nt], a_h[cur][mt],
                             b_h[cur][ng][sel], b_h[cur][ng][sel + 2]);
                }
            #pragma unroll
            for (int mt = 0; mt < 2; mt++)
                #pragma unroll
                for (int nt = 0; nt < 4; nt++) {
                    const int ng = nt >> 1, sel = nt & 1;
                    mma16816(acc[mt][nt], a_h[cur][mt],
                             b_l[cur][ng][sel], b_l[cur][ng][sel + 2]);
                }
            #pragma unroll
            for (int mt = 0; mt < 2; mt++)
                #pragma unroll
                for (int nt = 0; nt < 4; nt++) {
                    const int ng = nt >> 1, sel = nt & 1;
                    mma16816(acc[mt][nt], a_l[cur][mt],
                             b_h[cur][ng][sel], b_h[cur][ng][sel + 2]);
                }
        }
        __syncthreads();
    }

    // ---- epilogue ----
    const float alpha = scale ? __ldg(scale) : 1.0f;
    const int mrow = m0 + wm * 32 + (lane >> 2);
    #pragma unroll
    for (int mt = 0; mt < 2; mt++) {
        #pragma unroll
        for (int nt = 0; nt < 4; nt++) {
            const int n = n0 + wn * 32 + nt * 8 + 2 * (lane & 3);
            const float bv0 = bias ? bias[n]     : 0.0f;
            const float bv1 = bias ? bias[n + 1] : 0.0f;
            #pragma unroll
            for (int h = 0; h < 2; h++) {
                const long long m = (long long)(mrow + mt * 16 + h * 8);
                const float v0 = acc[mt][nt][2 * h + 0] * alpha + bv0;
                const float v1 = acc[mt][nt][2 * h + 1] * alpha + bv1;
                const size_t idx = (size_t)blockIdx.z * sC + m * ldc + n;
                if (OUT_MODE == 0) {
                    *(float2*)(C + idx) = make_float2(v0, v1);
                } else {
                    bf16 h0 = __float2bfloat16(v0), h1 = __float2bfloat16(v1);
                    bf16 l0 = __float2bfloat16(v0 - __bfloat162float(h0));
                    bf16 l1 = __float2bfloat16(v1 - __bfloat162float(h1));
                    *(__nv_bfloat162*)(Ch + idx) = __nv_bfloat162(h0, h1);
                    *(__nv_bfloat162*)(Cl + idx) = __nv_bfloat162(l0, l1);
                }
            }
        }
    }
}

// ---------------- softmax: warp/row, masked, writes fp32 + split bf16 ----------------
__global__ void __launch_bounds__(128)
softmax_kernel(float* __restrict__ attn, const int* __restrict__ lens,
               bf16* __restrict__ ah, bf16* __restrict__ al)
{
    int warp = (int)((blockIdx.x * blockDim.x + threadIdx.x) >> 5);
    int lane = threadIdx.x & 31;
    if (warp >= B_ * TQ) return;
    const int len = lens[warp / TQ];
    float4* row = (float4*)(attn + (size_t)warp * TK);

    float4 v[8];
    float mx = -INFINITY;
    #pragma unroll
    for (int i = 0; i < 8; i++) {
        v[i] = row[i * 32 + lane];
        int k = 4 * (i * 32 + lane);
        if (k + 0 < len) mx = fmaxf(mx, v[i].x);
        if (k + 1 < len) mx = fmaxf(mx, v[i].y);
        if (k + 2 < len) mx = fmaxf(mx, v[i].z);
        if (k + 3 < len) mx = fmaxf(mx, v[i].w);
    }
    #pragma unroll
    for (int o = 16; o > 0; o >>= 1)
        mx = fmaxf(mx, __shfl_xor_sync(0xFFFFFFFFu, mx, o));

    float sum = 0.0f;
    #pragma unroll
    for (int i = 0; i < 8; i++) {
        int k = 4 * (i * 32 + lane);
        v[i].x = (k + 0 < len) ? expf(v[i].x - mx) : 0.0f;
        v[i].y = (k + 1 < len) ? expf(v[i].y - mx) : 0.0f;
        v[i].z = (k + 2 < len) ? expf(v[i].z - mx) : 0.0f;
        v[i].w = (k + 3 < len) ? expf(v[i].w - mx) : 0.0f;
        sum += v[i].x + v[i].y + v[i].z + v[i].w;
    }
    #pragma unroll
    for (int o = 16; o > 0; o >>= 1)
        sum += __shfl_xor_sync(0xFFFFFFFFu, sum, o);

    const float inv = 1.0f / sum;
    uint2* rh = (uint2*)(ah + (size_t)warp * TK);
    uint2* rl = (uint2*)(al + (size_t)warp * TK);
    #pragma unroll
    for (int i = 0; i < 8; i++) {
        v[i].x *= inv; v[i].y *= inv; v[i].z *= inv; v[i].w *= inv;
        row[i * 32 + lane] = v[i];
        union { bf16 b[4]; uint2 u; } H, L;
        float xs[4] = {v[i].x, v[i].y, v[i].z, v[i].w};
        #pragma unroll
        for (int j = 0; j < 4; j++) {
            bf16 h = __float2bfloat16(xs[j]);
            H.b[j] = h;
            L.b[j] = __float2bfloat16(xs[j] - __bfloat162float(h));
        }
        rh[i * 32 + lane] = H.u;
        rl[i * 32 + lane] = L.u;
    }
}

// ---------------- launch ----------------
extern "C" void kernel_launch(void* const* d_in, const int* in_sizes, int n_in,
                              void* d_out, int out_size)
{
    const float *query = nullptr, *keys = nullptr, *Wq = nullptr,
                *bq = nullptr, *scale = nullptr;
    const int *lens = nullptr;
    for (int i = 0; i < n_in; i++) {
        switch (in_sizes[i]) {
            case B_ * TQ * DD: query = (const float*)d_in[i]; break;
            case B_ * TK * DD: keys  = (const float*)d_in[i]; break;
            case B_:           lens  = (const int*)  d_in[i]; break;
            case DD * DD:      Wq    = (const float*)d_in[i]; break;
            case DD:           bq    = (const float*)d_in[i]; break;
            case 1:            scale = (const float*)d_in[i]; break;
            default: break;
        }
    }

    bf16 *qh, *ql, *wh, *wl, *kh, *kl, *kth, *ktl, *qph, *qpl, *ah, *al;
    cudaGetSymbolAddress((void**)&qh,  g_qh);  cudaGetSymbolAddress((void**)&ql,  g_ql);
    cudaGetSymbolAddress((void**)&wh,  g_wh);  cudaGetSymbolAddress((void**)&wl,  g_wl);
    cudaGetSymbolAddress((void**)&kh,  g_kh);  cudaGetSymbolAddress((void**)&kl,  g_kl);
    cudaGetSymbolAddress((void**)&kth, g_kth); cudaGetSymbolAddress((void**)&ktl, g_ktl);
    cudaGetSymbolAddress((void**)&qph, g_qph); cudaGetSymbolAddress((void**)&qpl, g_qpl);
    cudaGetSymbolAddress((void**)&ah,  g_ah);  cudaGetSymbolAddress((void**)&al,  g_al);

    cudaFuncSetAttribute(mma_gemm<0,1>, cudaFuncAttributeMaxDynamicSharedMemorySize, SMEM_DYN);
    cudaFuncSetAttribute(mma_gemm<0,2>, cudaFuncAttributeMaxDynamicSharedMemorySize, SMEM_DYN);
    cudaFuncSetAttribute(mma_gemm<1,0>, cudaFuncAttributeMaxDynamicSharedMemorySize, SMEM_DYN);

    float* context = (float*)d_out;                         // B*TQ*DD
    float* attn    = (float*)d_out + (size_t)B_ * TQ * DD;  // B*TQ*TK

    // input splits
    split_kernel<<<(B_ * TQ * DD / 4 + 255) / 256, 256>>>(query, qh, ql, B_ * TQ * DD / 4);
    split_kernel<<<(DD * DD / 4 + 255) / 256, 256>>>(Wq, wh, wl, DD * DD / 4);
    ksplit_kernel<<<dim3(TK / 32, DD / 32, B_), 256>>>(keys, kh, kl, kth, ktl);

    // 1) Q' = query @ Wq^T + bq -> split bf16 directly (M=8192, N=512, K=512)
    mma_gemm<1,0><<<dim3(DD / 64, (B_ * TQ) / 128, 1), 256, SMEM_DYN>>>(
        qh, ql, 0, DD, wh, wl, 0, DD,
        nullptr, qph, qpl, 0, DD, DD, bq, nullptr, nullptr);

    // 2) scores = scale * Q'_b @ K_b^T -> fp32 attn; skip fully-masked N tiles
    mma_gemm<0,1><<<dim3(TK / 64, TQ / 128, B_), 256, SMEM_DYN>>>(
        qph, qpl, (long long)TQ * DD, DD,
        kh, kl, (long long)TK * DD, DD,
        attn, nullptr, nullptr, (long long)TQ * TK, TK, DD, nullptr, scale, lens);

    // 3) masked softmax (fp32 out + fused split; zeros all masked columns)
    softmax_kernel<<<(B_ * TQ * 32) / 128, 128>>>(attn, lens, ah, al);

    // 4) context = attn_b @ keysT_b^T -> fp32; truncate K to valid length
    mma_gemm<0,2><<<dim3(DD / 64, TQ / 128, B_), 256, SMEM_DYN>>>(
        ah, al, (long long)TQ * TK, TK,
        kth, ktl, (long long)DD * TK, TK,
        context, nullptr, nullptr, (long long)TQ * DD, DD, TK, nullptr, nullptr, lens);
}